// round 4
// baseline (speedup 1.0000x reference)
#include <cuda_runtime.h>
#include <cuda_bf16.h>

// Fused multi-LoRA expand:
//   out[perm[i], n] = scal[w] * sum_{k<r} x[perm[i], j*r + k] * W[w][n, k]
// where segment s = segment containing logical row i, w = weight_indices[s],
// r = lora_ranks[w], j = output slice containing column n. r==0 -> zeros.
//
// Tiling: 64 logical rows x 128 output cols per block, 256 threads,
// 4x8 register micro-tile per thread, K processed in chunks of 32.

#define TILE_M 64
#define TILE_N 128
#define KCHUNK 32
#define XS_STRIDE (TILE_M + 4)   // 68 floats; float4-aligned, conflict-lean
#define WS_STRIDE (TILE_N + 4)   // 132 floats

__global__ __launch_bounds__(256) void lora_expand_kernel(
    const float* __restrict__ x,            // (M, D)
    const float* __restrict__ weights,      // (L, N, max_rank)
    const int*   __restrict__ seg_indptr,   // (num_segments+1)
    const int*   __restrict__ weight_indices,
    const int*   __restrict__ lora_ranks,
    const float* __restrict__ scalings,
    const int*   __restrict__ permutation,  // (M)
    const int*   __restrict__ slice_offsets,// (num_slices+1)
    int num_segments, int num_slices,
    int M, int D, int N, int max_rank,
    float* __restrict__ out)                // (M, N)
{
    __shared__ float xs[KCHUNK * XS_STRIDE];  // [k][row]
    __shared__ float ws[KCHUNK * WS_STRIDE];  // [k][col]

    const int tid  = threadIdx.x;
    const int row0 = blockIdx.y * TILE_M;
    const int n0   = blockIdx.x * TILE_N;

    // Segment for this row tile (tiles never straddle segments: 64 | 2048)
    int seg = 0;
    while (seg + 1 < num_segments && seg_indptr[seg + 1] <= row0) seg++;
    const int w = weight_indices[seg];
    const int r = lora_ranks[w];

    const int tx = tid & 15;    // 16 col-groups of 8
    const int ty = tid >> 4;    // 16 row-groups of 4
    const int rowb = ty * 4;
    const int colb = tx * 8;

    if (r <= 0) {
        // rank-0 adapter: this tile of the output is zero (out is poisoned)
        const float4 z = make_float4(0.f, 0.f, 0.f, 0.f);
        #pragma unroll
        for (int a = 0; a < 4; a++) {
            int p = permutation[row0 + rowb + a];
            float4* o = reinterpret_cast<float4*>(out + (size_t)p * N + n0 + colb);
            o[0] = z; o[1] = z;
        }
        return;
    }

    const float scal = scalings[w];

    // Output slice for this column tile (tiles never straddle slices)
    int j = 0;
    while (j + 1 < num_slices && slice_offsets[j + 1] <= n0) j++;
    const int xbase = j * r;   // x is packed at slice_id * cur_rank

    const float* Wb = weights + (size_t)w * N * max_rank;

    float acc[4][8];
    #pragma unroll
    for (int a = 0; a < 4; a++)
        #pragma unroll
        for (int b = 0; b < 8; b++) acc[a][b] = 0.f;

    const int kl = tid & 31;        // k lane within chunk
    const int gb = tid >> 5;        // 0..7 group for fills

    for (int k0 = 0; k0 < r; k0 += KCHUNK) {
        const int kc = min(KCHUNK, r - k0);
        __syncthreads();   // protect previous chunk's smem reads

        // Fill xs[k][row] = x[perm[row], xbase + k0 + k]  (zero-pad k >= kc)
        #pragma unroll
        for (int rr = gb; rr < TILE_M; rr += 8) {
            int p = permutation[row0 + rr];
            float v = (kl < kc) ? x[(size_t)p * D + xbase + k0 + kl] : 0.f;
            xs[kl * XS_STRIDE + rr] = v;
        }
        // Fill ws[k][col] = W[n0+col][k0+k]
        #pragma unroll
        for (int c = gb; c < TILE_N; c += 8) {
            float v = (kl < kc) ? Wb[(size_t)(n0 + c) * max_rank + k0 + kl] : 0.f;
            ws[kl * WS_STRIDE + c] = v;
        }
        __syncthreads();

        #pragma unroll 8
        for (int k = 0; k < KCHUNK; k++) {
            float4 xa  = *reinterpret_cast<const float4*>(&xs[k * XS_STRIDE + rowb]);
            float4 wb0 = *reinterpret_cast<const float4*>(&ws[k * WS_STRIDE + colb]);
            float4 wb1 = *reinterpret_cast<const float4*>(&ws[k * WS_STRIDE + colb + 4]);
            float xr[4] = {xa.x, xa.y, xa.z, xa.w};
            float wc[8] = {wb0.x, wb0.y, wb0.z, wb0.w, wb1.x, wb1.y, wb1.z, wb1.w};
            #pragma unroll
            for (int a = 0; a < 4; a++)
                #pragma unroll
                for (int b = 0; b < 8; b++)
                    acc[a][b] = fmaf(xr[a], wc[b], acc[a][b]);
        }
    }

    // Epilogue: scale + scatter to physical rows
    #pragma unroll
    for (int a = 0; a < 4; a++) {
        int p = permutation[row0 + rowb + a];
        float4 v0 = make_float4(acc[a][0] * scal, acc[a][1] * scal,
                                acc[a][2] * scal, acc[a][3] * scal);
        float4 v1 = make_float4(acc[a][4] * scal, acc[a][5] * scal,
                                acc[a][6] * scal, acc[a][7] * scal);
        float4* o = reinterpret_cast<float4*>(out + (size_t)p * N + n0 + colb);
        o[0] = v0; o[1] = v1;
    }
}

extern "C" void kernel_launch(void* const* d_in, const int* in_sizes, int n_in,
                              void* d_out, int out_size) {
    const float* x              = (const float*)d_in[0];
    const float* weights        = (const float*)d_in[1];
    const int*   seg_indptr     = (const int*)d_in[2];
    const int*   weight_indices = (const int*)d_in[3];
    const int*   lora_ranks     = (const int*)d_in[4];
    const float* scalings       = (const float*)d_in[5];
    const int*   permutation    = (const int*)d_in[6];
    const int*   slice_offsets  = (const int*)d_in[7];

    const int M            = in_sizes[6];
    const int D            = in_sizes[0] / M;
    const int num_segments = in_sizes[2] - 1;
    const int num_slices   = in_sizes[7] - 1;
    const int N            = out_size / M;
    const int max_rank     = D / num_slices;

    dim3 grid(N / TILE_N, M / TILE_M);
    lora_expand_kernel<<<grid, 256>>>(
        x, weights, seg_indptr, weight_indices, lora_ranks, scalings,
        permutation, slice_offsets, num_segments, num_slices,
        M, D, N, max_rank, (float*)d_out);
}

// round 8
// speedup vs baseline: 1.4269x; 1.4269x over previous
#include <cuda_runtime.h>
#include <cuda_bf16.h>
#include <cstdint>

// ============================================================================
// Fused multi-LoRA expand via mma.sync bf16 (sm_80-compatible PTX, tensor pipe):
//   out[perm[i], n] = scal[w] * sum_{k<r} x[perm[i], j*r + k] * W[w][n, k]
// fp32 emulated with bf16 hi/lo split: D = Ah*Bh + Ah*Bl + Al*Bh (f32 accum)
// Tile: 128 rows x 128 cols per block, 8 warps, each warp 64x32 via m16n8k16.
// ============================================================================

#define TILE_M 128
#define TILE_N 128
#define STRIDE 72                     // bf16 per SMEM row (64 + 8 pad)
#define ROWB   (STRIDE * 2)           // 144 bytes per row
#define TILE_BYTES (TILE_M * ROWB)    // 18432 B per hi/lo tile
#define DYN_SMEM (4 * TILE_BYTES + 32)

__device__ __forceinline__ uint32_t smem_u32(const void* p) {
    uint32_t a;
    asm("{ .reg .u64 t; cvta.to.shared.u64 t, %1; cvt.u32.u64 %0, t; }" : "=r"(a) : "l"(p));
    return a;
}
__device__ __forceinline__ void ldsm_x4(uint32_t& r0, uint32_t& r1,
                                        uint32_t& r2, uint32_t& r3, uint32_t addr) {
    asm volatile("ldmatrix.sync.aligned.m8n8.x4.shared.b16 {%0,%1,%2,%3}, [%4];"
                 : "=r"(r0), "=r"(r1), "=r"(r2), "=r"(r3) : "r"(addr));
}
__device__ __forceinline__ void mma_bf16(float* c, const uint32_t* a, const uint32_t* b) {
    asm volatile(
        "mma.sync.aligned.m16n8k16.row.col.f32.bf16.bf16.f32 "
        "{%0,%1,%2,%3}, {%4,%5,%6,%7}, {%8,%9}, {%0,%1,%2,%3};"
        : "+f"(c[0]), "+f"(c[1]), "+f"(c[2]), "+f"(c[3])
        : "r"(a[0]), "r"(a[1]), "r"(a[2]), "r"(a[3]), "r"(b[0]), "r"(b[1]));
}
__device__ __forceinline__ uint32_t pack_bf16(float a, float b) {
    __nv_bfloat162 t = __floats2bfloat162_rn(a, b);
    return *reinterpret_cast<uint32_t*>(&t);
}
__device__ __forceinline__ float bf16_round(float a) {
    return __bfloat162float(__float2bfloat16(a));
}

__global__ __launch_bounds__(256) void lora_mma_kernel(
    const float* __restrict__ x,            // (M, D)
    const float* __restrict__ weights,      // (L, N, max_rank)
    const int*   __restrict__ seg_indptr,
    const int*   __restrict__ weight_indices,
    const int*   __restrict__ lora_ranks,
    const float* __restrict__ scalings,
    const int*   __restrict__ permutation,
    const int*   __restrict__ slice_offsets,
    int num_segments, int num_slices,
    int M, int D, int N, int max_rank,
    float* __restrict__ out)
{
    extern __shared__ char dyn[];
    __shared__ int ps[TILE_M];

    const int tid  = threadIdx.x;
    const int wid  = tid >> 5;
    const int lid  = tid & 31;
    const int row0 = blockIdx.y * TILE_M;
    const int n0   = blockIdx.x * TILE_N;

    // Segment / adapter for this row tile (128 divides segment length 2048)
    int seg = 0;
    while (seg + 1 < num_segments && seg_indptr[seg + 1] <= row0) seg++;
    const int w = weight_indices[seg];
    const int r = lora_ranks[w];

    if (tid < TILE_M) ps[tid] = permutation[row0 + tid];
    __syncthreads();

    if (r <= 0) {   // rank-0 adapter: zero this tile (out is poisoned)
        const float4 z = make_float4(0.f, 0.f, 0.f, 0.f);
        const int row  = tid >> 1;
        float4* o = reinterpret_cast<float4*>(
            out + (size_t)ps[row] * N + n0 + (tid & 1) * 64);
        #pragma unroll
        for (int i = 0; i < 16; i++) o[i] = z;
        return;
    }

    // Output slice for this column tile (128 divides slice length 2048)
    int j = 0;
    while (j + 1 < num_slices && slice_offsets[j + 1] <= n0) j++;
    const int   xbase = j * r;
    const float scal  = scalings[w];
    const int   nk16  = (r + 15) >> 4;
    const int   kpad  = nk16 << 4;

    char* aHi = dyn;
    char* aLo = dyn + TILE_BYTES;
    char* bHi = dyn + 2 * TILE_BYTES;
    char* bLo = dyn + 3 * TILE_BYTES;

    // ---- Load + split A: aX[row][k] = x[ps[row]*D + xbase + k]
    for (int idx = tid; idx < TILE_M * 16; idx += 256) {
        const int row = idx >> 4;
        const int kq  = (idx & 15) << 2;
        if (kq >= kpad) continue;
        float4 v = make_float4(0.f, 0.f, 0.f, 0.f);
        const float* xr = x + (size_t)ps[row] * D + xbase;
        if (kq + 3 < r) {
            v = *reinterpret_cast<const float4*>(xr + kq);
        } else {
            if (kq + 0 < r) v.x = xr[kq + 0];
            if (kq + 1 < r) v.y = xr[kq + 1];
            if (kq + 2 < r) v.z = xr[kq + 2];
            if (kq + 3 < r) v.w = xr[kq + 3];
        }
        float hx = bf16_round(v.x), hy = bf16_round(v.y);
        float hz = bf16_round(v.z), hw = bf16_round(v.w);
        const uint32_t off = row * ROWB + kq * 2;
        *reinterpret_cast<uint2*>(aHi + off) =
            make_uint2(pack_bf16(hx, hy), pack_bf16(hz, hw));
        *reinterpret_cast<uint2*>(aLo + off) =
            make_uint2(pack_bf16(v.x - hx, v.y - hy), pack_bf16(v.z - hz, v.w - hw));
    }

    // ---- Load + split B: bX[c][k] = W[w][n0+c][k]  (n-major rows, k contiguous)
    const float* Wb = weights + (size_t)w * N * max_rank;
    for (int idx = tid; idx < TILE_N * 16; idx += 256) {
        const int row = idx >> 4;
        const int kq  = (idx & 15) << 2;
        if (kq >= kpad) continue;
        float4 v = make_float4(0.f, 0.f, 0.f, 0.f);
        const float* wr = Wb + (size_t)(n0 + row) * max_rank;
        if (kq + 3 < r) {
            v = *reinterpret_cast<const float4*>(wr + kq);
        } else {
            if (kq + 0 < r) v.x = wr[kq + 0];
            if (kq + 1 < r) v.y = wr[kq + 1];
            if (kq + 2 < r) v.z = wr[kq + 2];
            if (kq + 3 < r) v.w = wr[kq + 3];
        }
        float hx = bf16_round(v.x), hy = bf16_round(v.y);
        float hz = bf16_round(v.z), hw = bf16_round(v.w);
        const uint32_t off = row * ROWB + kq * 2;
        *reinterpret_cast<uint2*>(bHi + off) =
            make_uint2(pack_bf16(hx, hy), pack_bf16(hz, hw));
        *reinterpret_cast<uint2*>(bLo + off) =
            make_uint2(pack_bf16(v.x - hx, v.y - hy), pack_bf16(v.z - hz, v.w - hw));
    }
    __syncthreads();

    // ---- Warp tiling: 2 (m) x 4 (n) warps, each 64 rows x 32 cols
    const int warp_m = wid & 1;
    const int warp_n = wid >> 1;

    float acc[4][4][4];
    #pragma unroll
    for (int mi = 0; mi < 4; mi++)
        #pragma unroll
        for (int ni = 0; ni < 4; ni++)
            #pragma unroll
            for (int e = 0; e < 4; e++) acc[mi][ni][e] = 0.f;

    // ldmatrix lane address offsets (bytes), within each hi/lo tile:
    //  A x4: lanes 0-15 -> rows (lid&15) @k0 ; lanes 16-31 -> same rows @k0+8
    //  B x4: lanes map to (n = (lid&7) + ((lid>>4)<<3), koff = ((lid>>3)&1)*8)
    const uint32_t aLane = (uint32_t)((warp_m * 64 + (lid & 15)) * ROWB
                                      + ((lid >> 4) << 3) * 2);
    const uint32_t bLane = (uint32_t)((warp_n * 32 + (lid & 7) + ((lid >> 4) << 3)) * ROWB
                                      + (((lid >> 3) & 1) << 3) * 2);

    const uint32_t aBaseArr[3] = { smem_u32(aHi), smem_u32(aHi), smem_u32(aLo) };
    const uint32_t bBaseArr[3] = { smem_u32(bHi), smem_u32(bLo), smem_u32(bHi) };

    #pragma unroll
    for (int p = 0; p < 3; p++) {
        const uint32_t aB = aBaseArr[p] + aLane;
        const uint32_t bB = bBaseArr[p] + bLane;
        for (int kc = 0; kc < nk16; kc++) {
            const uint32_t kb = (uint32_t)kc * 32;   // 16 k * 2B
            uint32_t afr[4][4];
            #pragma unroll
            for (int mi = 0; mi < 4; mi++)
                ldsm_x4(afr[mi][0], afr[mi][1], afr[mi][2], afr[mi][3],
                        aB + (uint32_t)(mi * 16 * ROWB) + kb);
            uint32_t bfr[4][2];
            #pragma unroll
            for (int nb = 0; nb < 2; nb++) {
                uint32_t r0, r1, r2, r3;
                ldsm_x4(r0, r1, r2, r3, bB + (uint32_t)(nb * 16 * ROWB) + kb);
                bfr[nb * 2 + 0][0] = r0; bfr[nb * 2 + 0][1] = r1;
                bfr[nb * 2 + 1][0] = r2; bfr[nb * 2 + 1][1] = r3;
            }
            #pragma unroll
            for (int mi = 0; mi < 4; mi++)
                #pragma unroll
                for (int ni = 0; ni < 4; ni++)
                    mma_bf16(acc[mi][ni], afr[mi], bfr[ni]);
        }
    }

    // ---- Epilogue: scale + scatter float2 stores
    const int gID = lid >> 2;
    const int tIG = lid & 3;
    #pragma unroll
    for (int mi = 0; mi < 4; mi++) {
        const int rowa = warp_m * 64 + mi * 16 + gID;
        float* oa = out + (size_t)ps[rowa]     * N + n0 + warp_n * 32;
        float* ob = out + (size_t)ps[rowa + 8] * N + n0 + warp_n * 32;
        #pragma unroll
        for (int ni = 0; ni < 4; ni++) {
            const int col = ni * 8 + tIG * 2;
            *reinterpret_cast<float2*>(oa + col) =
                make_float2(acc[mi][ni][0] * scal, acc[mi][ni][1] * scal);
            *reinterpret_cast<float2*>(ob + col) =
                make_float2(acc[mi][ni][2] * scal, acc[mi][ni][3] * scal);
        }
    }
}

extern "C" void kernel_launch(void* const* d_in, const int* in_sizes, int n_in,
                              void* d_out, int out_size) {
    const float* x              = (const float*)d_in[0];
    const float* weights        = (const float*)d_in[1];
    const int*   seg_indptr     = (const int*)d_in[2];
    const int*   weight_indices = (const int*)d_in[3];
    const int*   lora_ranks     = (const int*)d_in[4];
    const float* scalings       = (const float*)d_in[5];
    const int*   permutation    = (const int*)d_in[6];
    const int*   slice_offsets  = (const int*)d_in[7];

    const int M            = in_sizes[6];
    const int D            = in_sizes[0] / M;
    const int num_segments = in_sizes[2] - 1;
    const int num_slices   = in_sizes[7] - 1;
    const int N            = out_size / M;
    const int max_rank     = D / num_slices;

    cudaFuncSetAttribute(lora_mma_kernel,
                         cudaFuncAttributeMaxDynamicSharedMemorySize, DYN_SMEM);

    dim3 grid(N / TILE_N, M / TILE_M);
    lora_mma_kernel<<<grid, 256, DYN_SMEM>>>(
        x, weights, seg_indptr, weight_indices, lora_ranks, scalings,
        permutation, slice_offsets, num_segments, num_slices,
        M, D, N, max_rank, (float*)d_out);
}

// round 13
// speedup vs baseline: 2.1051x; 1.4753x over previous
#include <cuda_runtime.h>
#include <cuda_bf16.h>
#include <cstdint>

// ============================================================================
// Fused multi-LoRA expand via mma.sync bf16 hi/lo split (tensor pipe):
//   out[perm[i], n] = scal[w] * sum_{k<r} x[perm[i], j*r + k] * W[w][n, k]
// D = Ah*Bh + Ah*Bl + Al*Bh (fp32 accum) -> ~1e-5 rel error.
// Strip-mined: each CTA holds one 128-col B tile and pipelines NT=4 row tiles
// of 128 rows with cp.async (A tile t+1 staged while tile t computes).
// ============================================================================

#define TILE_M 128
#define TILE_N 128
#define NT     4                      // row tiles per CTA strip
#define STRIDE 72                     // bf16 per SMEM row (64 + 8 pad)
#define ROWB   (STRIDE * 2)           // 144 bytes per bf16 row
#define TILE_BYTES (TILE_M * ROWB)    // 18432 B per hi/lo tile
#define SF     68                     // fp32 staging floats per row
#define SROWB  (SF * 4)               // 272 B per staging row
#define STAGE_BYTES (TILE_M * SROWB)  // 34816 B
// layout: [aHi][aLo][bHi][bLo][stage][ps]
#define DYN_SMEM (4 * TILE_BYTES + STAGE_BYTES + NT * TILE_M * 4 + 32)

__device__ __forceinline__ uint32_t smem_u32(const void* p) {
    uint32_t a;
    asm("{ .reg .u64 t; cvta.to.shared.u64 t, %1; cvt.u32.u64 %0, t; }" : "=r"(a) : "l"(p));
    return a;
}
__device__ __forceinline__ void ldsm_x4(uint32_t& r0, uint32_t& r1,
                                        uint32_t& r2, uint32_t& r3, uint32_t addr) {
    asm volatile("ldmatrix.sync.aligned.m8n8.x4.shared.b16 {%0,%1,%2,%3}, [%4];"
                 : "=r"(r0), "=r"(r1), "=r"(r2), "=r"(r3) : "r"(addr));
}
__device__ __forceinline__ void mma_bf16(float* c, const uint32_t* a, const uint32_t* b) {
    asm volatile(
        "mma.sync.aligned.m16n8k16.row.col.f32.bf16.bf16.f32 "
        "{%0,%1,%2,%3}, {%4,%5,%6,%7}, {%8,%9}, {%0,%1,%2,%3};"
        : "+f"(c[0]), "+f"(c[1]), "+f"(c[2]), "+f"(c[3])
        : "r"(a[0]), "r"(a[1]), "r"(a[2]), "r"(a[3]), "r"(b[0]), "r"(b[1]));
}
__device__ __forceinline__ void cp_async16(uint32_t dst, const void* src, uint32_t bytes) {
    asm volatile("cp.async.cg.shared.global [%0], [%1], 16, %2;"
                 :: "r"(dst), "l"(src), "r"(bytes) : "memory");
}
#define CP_COMMIT() asm volatile("cp.async.commit_group;" ::: "memory")
#define CP_WAIT0()  asm volatile("cp.async.wait_group 0;" ::: "memory")

__device__ __forceinline__ uint32_t pack_bf16(float a, float b) {
    __nv_bfloat162 t = __floats2bfloat162_rn(a, b);
    return *reinterpret_cast<uint32_t*>(&t);
}
__device__ __forceinline__ float bf16_round(float a) {
    return __bfloat162float(__float2bfloat16(a));
}

__global__ __launch_bounds__(256, 2) void lora_mma_pipe_kernel(
    const float* __restrict__ x,            // (M, D)
    const float* __restrict__ weights,      // (L, N, max_rank)
    const int*   __restrict__ seg_indptr,
    const int*   __restrict__ weight_indices,
    const int*   __restrict__ lora_ranks,
    const float* __restrict__ scalings,
    const int*   __restrict__ permutation,
    const int*   __restrict__ slice_offsets,
    int num_segments, int num_slices,
    int M, int D, int N, int max_rank,
    float* __restrict__ out)
{
    extern __shared__ char dyn[];
    char* aHi   = dyn;
    char* aLo   = dyn + TILE_BYTES;
    char* bHi   = dyn + 2 * TILE_BYTES;
    char* bLo   = dyn + 3 * TILE_BYTES;
    char* stage = dyn + 4 * TILE_BYTES;
    int*  ps    = reinterpret_cast<int*>(dyn + 4 * TILE_BYTES + STAGE_BYTES);

    const int tid   = threadIdx.x;
    const int wid   = tid >> 5;
    const int lid   = tid & 31;
    const int strip = blockIdx.y * (TILE_M * NT);
    const int n0    = blockIdx.x * TILE_N;

    // Segment / adapter for this strip (TILE_M*NT divides segment length)
    int seg = 0;
    while (seg + 1 < num_segments && seg_indptr[seg + 1] <= strip) seg++;
    const int w = weight_indices[seg];
    const int r = lora_ranks[w];

    // Preload permutation for the whole strip
    for (int i = tid; i < TILE_M * NT; i += 256) ps[i] = permutation[strip + i];
    __syncthreads();

    if (r <= 0) {   // rank-0 adapter: zero the strip (out is poisoned)
        const float4 z = make_float4(0.f, 0.f, 0.f, 0.f);
        for (int t = 0; t < NT; t++) {
            const int row = (tid >> 1) + t * TILE_M;
            float4* o = reinterpret_cast<float4*>(
                out + (size_t)ps[row] * N + n0 + (tid & 1) * 64);
            #pragma unroll
            for (int i = 0; i < 16; i++) o[i] = z;
        }
        return;
    }

    int j = 0;
    while (j + 1 < num_slices && slice_offsets[j + 1] <= n0) j++;
    const int   xbase = j * r;
    const float scal  = scalings[w];
    const int   nk16  = (r + 15) >> 4;
    const int   kpad  = nk16 << 4;

    const uint32_t stage_b = smem_u32(stage);

    // ---- stage A tile t via cp.async into fp32 staging
    auto stage_A = [&](int t) {
        const int rbase = t * TILE_M;
        for (int idx = tid; idx < TILE_M * 16; idx += 256) {
            const int row = idx >> 4;
            const int kq  = (idx & 15) << 2;
            if (kq >= kpad) continue;
            const float* xr = x + (size_t)ps[rbase + row] * D + xbase;
            int   rem   = r - kq;
            int   bytes = rem >= 4 ? 16 : (rem > 0 ? rem * 4 : 0);
            int   soff  = (kq < r) ? kq : 0;
            cp_async16(stage_b + row * SROWB + kq * 4, xr + soff, (uint32_t)bytes);
        }
        CP_COMMIT();
    };

    // ---- convert staging -> bf16 hi/lo
    auto convert_A = [&]() {
        for (int idx = tid; idx < TILE_M * 16; idx += 256) {
            const int row = idx >> 4;
            const int kq  = (idx & 15) << 2;
            if (kq >= kpad) continue;
            float4 v = *reinterpret_cast<const float4*>(stage + row * SROWB + kq * 4);
            float hx = bf16_round(v.x), hy = bf16_round(v.y);
            float hz = bf16_round(v.z), hw = bf16_round(v.w);
            const uint32_t off = row * ROWB + kq * 2;
            *reinterpret_cast<uint2*>(aHi + off) =
                make_uint2(pack_bf16(hx, hy), pack_bf16(hz, hw));
            *reinterpret_cast<uint2*>(aLo + off) =
                make_uint2(pack_bf16(v.x - hx, v.y - hy), pack_bf16(v.z - hz, v.w - hw));
        }
    };

    // ---- Prologue: kick off A0, then load+convert B (overlaps A0 flight)
    stage_A(0);

    const float* Wb = weights + (size_t)w * N * max_rank;
    for (int idx = tid; idx < TILE_N * 16; idx += 256) {
        const int row = idx >> 4;
        const int kq  = (idx & 15) << 2;
        if (kq >= kpad) continue;
        float4 v = make_float4(0.f, 0.f, 0.f, 0.f);
        const float* wr = Wb + (size_t)(n0 + row) * max_rank;
        if (kq + 3 < r) {
            v = *reinterpret_cast<const float4*>(wr + kq);
        } else {
            if (kq + 0 < r) v.x = wr[kq + 0];
            if (kq + 1 < r) v.y = wr[kq + 1];
            if (kq + 2 < r) v.z = wr[kq + 2];
            if (kq + 3 < r) v.w = wr[kq + 3];
        }
        float hx = bf16_round(v.x), hy = bf16_round(v.y);
        float hz = bf16_round(v.z), hw = bf16_round(v.w);
        const uint32_t off = row * ROWB + kq * 2;
        *reinterpret_cast<uint2*>(bHi + off) =
            make_uint2(pack_bf16(hx, hy), pack_bf16(hz, hw));
        *reinterpret_cast<uint2*>(bLo + off) =
            make_uint2(pack_bf16(v.x - hx, v.y - hy), pack_bf16(v.z - hz, v.w - hw));
    }

    // ---- ldmatrix lane offsets (warp tiling: 2(m) x 4(n), warp tile 64x32)
    const int warp_m = wid & 1;
    const int warp_n = wid >> 1;
    const uint32_t aLane = (uint32_t)((warp_m * 64 + (lid & 15)) * ROWB
                                      + ((lid >> 4) << 3) * 2);
    const uint32_t bLane = (uint32_t)((warp_n * 32 + (lid & 7) + ((lid >> 4) << 3)) * ROWB
                                      + (((lid >> 3) & 1) << 3) * 2);
    const uint32_t aBaseArr[3] = { smem_u32(aHi) + aLane, smem_u32(aHi) + aLane,
                                   smem_u32(aLo) + aLane };
    const uint32_t bBaseArr[3] = { smem_u32(bHi) + bLane, smem_u32(bLo) + bLane,
                                   smem_u32(bHi) + bLane };
    const int gID = lid >> 2;
    const int tIG = lid & 3;

    // ---- Main pipelined loop over row tiles
    for (int t = 0; t < NT; t++) {
        CP_WAIT0();
        __syncthreads();            // staging(t) complete; bf16 A free (prev compute done)
        convert_A();
        __syncthreads();            // bf16 A(t) ready
        if (t + 1 < NT) stage_A(t + 1);   // in flight during compute + stores

        float acc[4][4][4];
        #pragma unroll
        for (int mi = 0; mi < 4; mi++)
            #pragma unroll
            for (int ni = 0; ni < 4; ni++)
                #pragma unroll
                for (int e = 0; e < 4; e++) acc[mi][ni][e] = 0.f;

        #pragma unroll
        for (int p = 0; p < 3; p++) {
            const uint32_t aB = aBaseArr[p];
            const uint32_t bB = bBaseArr[p];
            for (int kc = 0; kc < nk16; kc++) {
                const uint32_t kb = (uint32_t)kc * 32;
                uint32_t afr[4][4];
                #pragma unroll
                for (int mi = 0; mi < 4; mi++)
                    ldsm_x4(afr[mi][0], afr[mi][1], afr[mi][2], afr[mi][3],
                            aB + (uint32_t)(mi * 16 * ROWB) + kb);
                uint32_t bfr[4][2];
                #pragma unroll
                for (int nb = 0; nb < 2; nb++) {
                    uint32_t r0, r1, r2, r3;
                    ldsm_x4(r0, r1, r2, r3, bB + (uint32_t)(nb * 16 * ROWB) + kb);
                    bfr[nb * 2 + 0][0] = r0; bfr[nb * 2 + 0][1] = r1;
                    bfr[nb * 2 + 1][0] = r2; bfr[nb * 2 + 1][1] = r3;
                }
                #pragma unroll
                for (int mi = 0; mi < 4; mi++)
                    #pragma unroll
                    for (int ni = 0; ni < 4; ni++)
                        mma_bf16(acc[mi][ni], afr[mi], bfr[ni]);
            }
        }

        // Epilogue: scale + scatter
        const int rbase = t * TILE_M;
        #pragma unroll
        for (int mi = 0; mi < 4; mi++) {
            const int rowa = warp_m * 64 + mi * 16 + gID;
            float* oa = out + (size_t)ps[rbase + rowa]     * N + n0 + warp_n * 32;
            float* ob = out + (size_t)ps[rbase + rowa + 8] * N + n0 + warp_n * 32;
            #pragma unroll
            for (int ni = 0; ni < 4; ni++) {
                const int col = ni * 8 + tIG * 2;
                *reinterpret_cast<float2*>(oa + col) =
                    make_float2(acc[mi][ni][0] * scal, acc[mi][ni][1] * scal);
                *reinterpret_cast<float2*>(ob + col) =
                    make_float2(acc[mi][ni][2] * scal, acc[mi][ni][3] * scal);
            }
        }
    }
}

extern "C" void kernel_launch(void* const* d_in, const int* in_sizes, int n_in,
                              void* d_out, int out_size) {
    const float* x              = (const float*)d_in[0];
    const float* weights        = (const float*)d_in[1];
    const int*   seg_indptr     = (const int*)d_in[2];
    const int*   weight_indices = (const int*)d_in[3];
    const int*   lora_ranks     = (const int*)d_in[4];
    const float* scalings       = (const float*)d_in[5];
    const int*   permutation    = (const int*)d_in[6];
    const int*   slice_offsets  = (const int*)d_in[7];

    const int M            = in_sizes[6];
    const int D            = in_sizes[0] / M;
    const int num_segments = in_sizes[2] - 1;
    const int num_slices   = in_sizes[7] - 1;
    const int N            = out_size / M;
    const int max_rank     = D / num_slices;

    cudaFuncSetAttribute(lora_mma_pipe_kernel,
                         cudaFuncAttributeMaxDynamicSharedMemorySize, DYN_SMEM);

    dim3 grid(N / TILE_N, M / (TILE_M * NT));
    lora_mma_pipe_kernel<<<grid, 256, DYN_SMEM>>>(
        x, weights, seg_indptr, weight_indices, lora_ranks, scalings,
        permutation, slice_offsets, num_segments, num_slices,
        M, D, N, max_rank, (float*)d_out);
}

// round 15
// speedup vs baseline: 2.1399x; 1.0166x over previous
#include <cuda_runtime.h>
#include <cuda_bf16.h>
#include <cstdint>

// ============================================================================
// Fused multi-LoRA expand, 3-kernel pipeline:
//  K1: split x (permuted gather, slice-packed, zero-padded) -> bf16 hi/lo scratch
//  K2: split W -> bf16 hi/lo scratch
//  K3: GEMM via mma.sync bf16 (Ah*Bh + Ah*Bl + Al*Bh, fp32 accum ~1e-5 err),
//      strip-mined (NT row tiles per CTA), double-buffered cp.async A pipeline.
// ============================================================================

#define TILE_M 128
#define TILE_N 128
#define NT     4
#define STRIDE 72                     // bf16 per SMEM row (64 + 8 pad)
#define ROWB   (STRIDE * 2)           // 144 B per row
#define TILE_BYTES (TILE_M * ROWB)    // 18432 B per hi/lo tile
// layout: [A0hi][A0lo][A1hi][A1lo][Bhi][Blo][ps]
#define DYN_SMEM (6 * TILE_BYTES + NT * TILE_M * 4 + 32)

// Static scratch sized for this problem (M=16384, D=128, L=8, N=4096, K=64)
#define MAX_M 16384
#define MAX_D 128
#define MAX_LNK (8 * 4096 * 64)
__device__ __nv_bfloat16 g_xhi[MAX_M * MAX_D];
__device__ __nv_bfloat16 g_xlo[MAX_M * MAX_D];
__device__ __nv_bfloat16 g_whi[MAX_LNK];
__device__ __nv_bfloat16 g_wlo[MAX_LNK];

__device__ __forceinline__ uint32_t smem_u32(const void* p) {
    uint32_t a;
    asm("{ .reg .u64 t; cvta.to.shared.u64 t, %1; cvt.u32.u64 %0, t; }" : "=r"(a) : "l"(p));
    return a;
}
__device__ __forceinline__ void ldsm_x4(uint32_t& r0, uint32_t& r1,
                                        uint32_t& r2, uint32_t& r3, uint32_t addr) {
    asm volatile("ldmatrix.sync.aligned.m8n8.x4.shared.b16 {%0,%1,%2,%3}, [%4];"
                 : "=r"(r0), "=r"(r1), "=r"(r2), "=r"(r3) : "r"(addr));
}
__device__ __forceinline__ void mma_bf16(float* c, const uint32_t* a, const uint32_t* b) {
    asm volatile(
        "mma.sync.aligned.m16n8k16.row.col.f32.bf16.bf16.f32 "
        "{%0,%1,%2,%3}, {%4,%5,%6,%7}, {%8,%9}, {%0,%1,%2,%3};"
        : "+f"(c[0]), "+f"(c[1]), "+f"(c[2]), "+f"(c[3])
        : "r"(a[0]), "r"(a[1]), "r"(a[2]), "r"(a[3]), "r"(b[0]), "r"(b[1]));
}
__device__ __forceinline__ void cp_async16(uint32_t dst, const void* src) {
    asm volatile("cp.async.cg.shared.global [%0], [%1], 16;"
                 :: "r"(dst), "l"(src) : "memory");
}
#define CP_COMMIT() asm volatile("cp.async.commit_group;" ::: "memory")
#define CP_WAIT0()  asm volatile("cp.async.wait_group 0;" ::: "memory")
#define CP_WAIT1()  asm volatile("cp.async.wait_group 1;" ::: "memory")

__device__ __forceinline__ uint32_t pack_bf16(float a, float b) {
    __nv_bfloat162 t = __floats2bfloat162_rn(a, b);
    return *reinterpret_cast<uint32_t*>(&t);
}
__device__ __forceinline__ float bf16_round(float a) {
    return __bfloat162float(__float2bfloat16(a));
}

// ---- K1: x -> logical-order, slice-packed, zero-padded bf16 hi/lo ----------
__global__ __launch_bounds__(256) void convert_x_kernel(
    const float* __restrict__ x, const int* __restrict__ seg_indptr,
    const int* __restrict__ weight_indices, const int* __restrict__ lora_ranks,
    const int* __restrict__ permutation,
    int num_segments, int M, int D, int max_rank)
{
    const int idx = blockIdx.x * 256 + threadIdx.x;   // M * 2 * 16 threads
    const int i = idx >> 5;
    if (i >= M) return;
    const int rem = idx & 31;
    const int j  = rem >> 4;
    const int kq = (rem & 15) << 2;

    int seg = 0;
    while (seg + 1 < num_segments && seg_indptr[seg + 1] <= i) seg++;
    const int w = weight_indices[seg];
    const int r = lora_ranks[w];

    float4 v = make_float4(0.f, 0.f, 0.f, 0.f);
    if (r > 0 && kq < r) {
        const float* xr = x + (size_t)permutation[i] * D + j * r;
        if (kq + 3 < r) {
            v = *reinterpret_cast<const float4*>(xr + kq);
        } else {
            v.x = xr[kq];
            if (kq + 1 < r) v.y = xr[kq + 1];
            if (kq + 2 < r) v.z = xr[kq + 2];
        }
    }
    float hx = bf16_round(v.x), hy = bf16_round(v.y);
    float hz = bf16_round(v.z), hw = bf16_round(v.w);
    const size_t off = (size_t)i * D + j * max_rank + kq;
    *reinterpret_cast<uint2*>(&g_xhi[off]) =
        make_uint2(pack_bf16(hx, hy), pack_bf16(hz, hw));
    *reinterpret_cast<uint2*>(&g_xlo[off]) =
        make_uint2(pack_bf16(v.x - hx, v.y - hy), pack_bf16(v.z - hz, v.w - hw));
}

// ---- K2: W -> zero-padded bf16 hi/lo ---------------------------------------
__global__ __launch_bounds__(256) void convert_w_kernel(
    const float* __restrict__ weights, const int* __restrict__ lora_ranks,
    int L, int N, int max_rank)
{
    const int idx = blockIdx.x * 256 + threadIdx.x;   // L * N * 16 threads
    const int kq = (idx & 15) << 2;
    const int n  = (idx >> 4) % N;
    const int l  = (idx >> 4) / N;
    if (l >= L) return;
    const int r = lora_ranks[l];

    float4 v = make_float4(0.f, 0.f, 0.f, 0.f);
    if (r > 0 && kq < r) {
        const float* wr = weights + ((size_t)l * N + n) * max_rank;
        if (kq + 3 < r) {
            v = *reinterpret_cast<const float4*>(wr + kq);
        } else {
            v.x = wr[kq];
            if (kq + 1 < r) v.y = wr[kq + 1];
            if (kq + 2 < r) v.z = wr[kq + 2];
        }
    }
    float hx = bf16_round(v.x), hy = bf16_round(v.y);
    float hz = bf16_round(v.z), hw = bf16_round(v.w);
    const size_t off = ((size_t)l * N + n) * 64 + kq;
    *reinterpret_cast<uint2*>(&g_whi[off]) =
        make_uint2(pack_bf16(hx, hy), pack_bf16(hz, hw));
    *reinterpret_cast<uint2*>(&g_wlo[off]) =
        make_uint2(pack_bf16(v.x - hx, v.y - hy), pack_bf16(v.z - hz, v.w - hw));
}

// ---- K3: GEMM ---------------------------------------------------------------
__global__ __launch_bounds__(256, 2) void lora_mma_pipe2_kernel(
    const int*   __restrict__ seg_indptr,
    const int*   __restrict__ weight_indices,
    const int*   __restrict__ lora_ranks,
    const float* __restrict__ scalings,
    const int*   __restrict__ permutation,
    const int*   __restrict__ slice_offsets,
    int num_segments, int num_slices,
    int M, int D, int N, int max_rank,
    float* __restrict__ out)
{
    extern __shared__ char dyn[];
    // [A0hi][A0lo][A1hi][A1lo][Bhi][Blo][ps]
    char* bHi = dyn + 4 * TILE_BYTES;
    char* bLo = dyn + 5 * TILE_BYTES;
    int*  ps  = reinterpret_cast<int*>(dyn + 6 * TILE_BYTES);

    const int tid   = threadIdx.x;
    const int wid   = tid >> 5;
    const int lid   = tid & 31;
    const int strip = blockIdx.y * (TILE_M * NT);
    const int n0    = blockIdx.x * TILE_N;

    int seg = 0;
    while (seg + 1 < num_segments && seg_indptr[seg + 1] <= strip) seg++;
    const int w = weight_indices[seg];
    const int r = lora_ranks[w];

    for (int i = tid; i < TILE_M * NT; i += 256) ps[i] = permutation[strip + i];

    if (r <= 0) {   // rank-0 adapter: zero the strip (out is poisoned)
        __syncthreads();
        const float4 z = make_float4(0.f, 0.f, 0.f, 0.f);
        for (int t = 0; t < NT; t++) {
            const int row = (tid >> 1) + t * TILE_M;
            float4* o = reinterpret_cast<float4*>(
                out + (size_t)ps[row] * N + n0 + (tid & 1) * 64);
            #pragma unroll
            for (int i = 0; i < 16; i++) o[i] = z;
        }
        return;
    }

    int j = 0;
    while (j + 1 < num_slices && slice_offsets[j + 1] <= n0) j++;
    const float scal = scalings[w];
    const int   nk16 = (r + 15) >> 4;
    const int   nch  = nk16 * 2;          // 16B chunks per row actually needed

    const uint32_t dyn_b = smem_u32(dyn);

    // stage A tile t (contiguous logical rows; no gather) into buffer t&1
    auto stage_A = [&](int t) {
        const uint32_t abase = dyn_b + (uint32_t)(t & 1) * (2 * TILE_BYTES);
        const size_t gbase = ((size_t)(strip + t * TILE_M)) * D + j * max_rank;
        for (int idx = tid; idx < TILE_M * nch; idx += 256) {
            const int row = idx / nch;
            const int c   = idx - row * nch;
            const uint32_t dst = abase + row * ROWB + c * 16;
            const size_t   src = gbase + (size_t)row * D + c * 8;
            cp_async16(dst,              &g_xhi[src]);
            cp_async16(dst + TILE_BYTES, &g_xlo[src]);
        }
        CP_COMMIT();
    };

    // ---- Prologue: A0, B, A1 as three commit groups
    stage_A(0);
    {
        const uint32_t bbase = smem_u32(bHi);
        const size_t gbase = ((size_t)w * N + n0) * 64;
        for (int idx = tid; idx < TILE_N * nch; idx += 256) {
            const int row = idx / nch;
            const int c   = idx - row * nch;
            const uint32_t dst = bbase + row * ROWB + c * 16;
            const size_t   src = gbase + (size_t)row * 64 + c * 8;
            cp_async16(dst,              &g_whi[src]);
            cp_async16(dst + TILE_BYTES, &g_wlo[src]);
        }
        CP_COMMIT();
    }
    if (NT > 1) stage_A(1);

    // ldmatrix lane offsets (warp tiling: 2(m) x 4(n), warp tile 64x32)
    const int warp_m = wid & 1;
    const int warp_n = wid >> 1;
    const uint32_t aLane = (uint32_t)((warp_m * 64 + (lid & 15)) * ROWB
                                      + ((lid >> 4) << 3) * 2);
    const uint32_t bLane = (uint32_t)((warp_n * 32 + (lid & 7) + ((lid >> 4) << 3)) * ROWB
                                      + (((lid >> 3) & 1) << 3) * 2);
    const uint32_t bHiL = smem_u32(bHi) + bLane;
    const uint32_t bLoL = smem_u32(bLo) + bLane;
    const int gID = lid >> 2;
    const int tIG = lid & 3;

    for (int t = 0; t < NT; t++) {
        if (t < NT - 1) { CP_WAIT1(); } else { CP_WAIT0(); }
        __syncthreads();              // A(t) + B visible to all warps

        const uint32_t aHiL = dyn_b + (uint32_t)(t & 1) * (2 * TILE_BYTES) + aLane;
        const uint32_t aLoL = aHiL + TILE_BYTES;
        const uint32_t aArr[3] = { aHiL, aHiL, aLoL };
        const uint32_t bArr[3] = { bHiL, bLoL, bHiL };

        float acc[4][4][4];
        #pragma unroll
        for (int mi = 0; mi < 4; mi++)
            #pragma unroll
            for (int ni = 0; ni < 4; ni++)
                #pragma unroll
                for (int e = 0; e < 4; e++) acc[mi][ni][e] = 0.f;

        #pragma unroll
        for (int p = 0; p < 3; p++) {
            const uint32_t aB = aArr[p];
            const uint32_t bB = bArr[p];
            for (int kc = 0; kc < nk16; kc++) {
                const uint32_t kb = (uint32_t)kc * 32;
                uint32_t afr[4][4];
                #pragma unroll
                for (int mi = 0; mi < 4; mi++)
                    ldsm_x4(afr[mi][0], afr[mi][1], afr[mi][2], afr[mi][3],
                            aB + (uint32_t)(mi * 16 * ROWB) + kb);
                uint32_t bfr[4][2];
                #pragma unroll
                for (int nb = 0; nb < 2; nb++) {
                    uint32_t r0, r1, r2, r3;
                    ldsm_x4(r0, r1, r2, r3, bB + (uint32_t)(nb * 16 * ROWB) + kb);
                    bfr[nb * 2 + 0][0] = r0; bfr[nb * 2 + 0][1] = r1;
                    bfr[nb * 2 + 1][0] = r2; bfr[nb * 2 + 1][1] = r3;
                }
                #pragma unroll
                for (int mi = 0; mi < 4; mi++)
                    #pragma unroll
                    for (int ni = 0; ni < 4; ni++)
                        mma_bf16(acc[mi][ni], afr[mi], bfr[ni]);
            }
        }

        __syncthreads();              // all warps done reading buffer t&1
        if (t + 2 < NT) stage_A(t + 2);   // refill it while we store

        const int rbase = t * TILE_M;
        #pragma unroll
        for (int mi = 0; mi < 4; mi++) {
            const int rowa = warp_m * 64 + mi * 16 + gID;
            float* oa = out + (size_t)ps[rbase + rowa]     * N + n0 + warp_n * 32;
            float* ob = out + (size_t)ps[rbase + rowa + 8] * N + n0 + warp_n * 32;
            #pragma unroll
            for (int ni = 0; ni < 4; ni++) {
                const int col = ni * 8 + tIG * 2;
                *reinterpret_cast<float2*>(oa + col) =
                    make_float2(acc[mi][ni][0] * scal, acc[mi][ni][1] * scal);
                *reinterpret_cast<float2*>(ob + col) =
                    make_float2(acc[mi][ni][2] * scal, acc[mi][ni][3] * scal);
            }
        }
    }
}

extern "C" void kernel_launch(void* const* d_in, const int* in_sizes, int n_in,
                              void* d_out, int out_size) {
    const float* x              = (const float*)d_in[0];
    const float* weights        = (const float*)d_in[1];
    const int*   seg_indptr     = (const int*)d_in[2];
    const int*   weight_indices = (const int*)d_in[3];
    const int*   lora_ranks     = (const int*)d_in[4];
    const float* scalings       = (const float*)d_in[5];
    const int*   permutation    = (const int*)d_in[6];
    const int*   slice_offsets  = (const int*)d_in[7];

    const int M            = in_sizes[6];
    const int D            = in_sizes[0] / M;
    const int num_segments = in_sizes[2] - 1;
    const int num_slices   = in_sizes[7] - 1;
    const int N            = out_size / M;
    const int max_rank     = D / num_slices;
    const int L            = in_sizes[1] / (N * max_rank);

    // K1: split x (gather + slice-pack + zero-pad)
    {
        const int threads = M * 2 * 16;
        convert_x_kernel<<<(threads + 255) / 256, 256>>>(
            x, seg_indptr, weight_indices, lora_ranks, permutation,
            num_segments, M, D, max_rank);
    }
    // K2: split W
    {
        const int threads = L * N * 16;
        convert_w_kernel<<<(threads + 255) / 256, 256>>>(
            weights, lora_ranks, L, N, max_rank);
    }
    // K3: GEMM
    cudaFuncSetAttribute(lora_mma_pipe2_kernel,
                         cudaFuncAttributeMaxDynamicSharedMemorySize, DYN_SMEM);
    dim3 grid(N / TILE_N, M / (TILE_M * NT));
    lora_mma_pipe2_kernel<<<grid, 256, DYN_SMEM>>>(
        seg_indptr, weight_indices, lora_ranks, scalings,
        permutation, slice_offsets, num_segments, num_slices,
        M, D, N, max_rank, (float*)d_out);
}